// round 8
// baseline (speedup 1.0000x reference)
#include <cuda_runtime.h>
#include <cstdint>

#define BATCH   32
#define LPTS    8192
#define MSEL    2048
#define CSIZE   4                   // CTAs per batch (cluster size)
#define CPTS    (LPTS / CSIZE)      // 2048 points per CTA
#define NTHR    256
#define PPT     (CPTS / NTHR)       // 8 points per thread
#define NPAIR   (PPT / 2)           // 4 packed pairs
#define NWARP   (NTHR / 32)         // 8 warps

typedef unsigned long long ull;

// Selected indices, written by fps kernel, read by gather kernel.
__device__ int g_fps_idx[BATCH * MSEL];

// ---- Blackwell packed f32x2 helpers (per-lane rn rounding == scalar) ------
__device__ __forceinline__ ull pk2(float lo, float hi) {
    ull r; asm("mov.b64 %0, {%1,%2};" : "=l"(r) : "f"(lo), "f"(hi)); return r;
}
__device__ __forceinline__ void upk2(ull v, float& lo, float& hi) {
    asm("mov.b64 {%0,%1}, %2;" : "=f"(lo), "=f"(hi) : "l"(v));
}
__device__ __forceinline__ ull add2(ull a, ull b) {
    ull r; asm("add.rn.f32x2 %0, %1, %2;" : "=l"(r) : "l"(a), "l"(b)); return r;
}
__device__ __forceinline__ ull mul2(ull a, ull b) {
    ull r; asm("mul.rn.f32x2 %0, %1, %2;" : "=l"(r) : "l"(a), "l"(b)); return r;
}
__device__ __forceinline__ ull fma2(ull a, ull b, ull c) {
    ull r; asm("fma.rn.f32x2 %0, %1, %2, %3;" : "=l"(r) : "l"(a), "l"(b), "l"(c)); return r;
}

__device__ __forceinline__ unsigned smem_u32(const void* p) {
    unsigned a;
    asm("{ .reg .u64 t; cvta.to.shared.u64 t, %1; cvt.u32.u64 %0, t; }"
        : "=r"(a) : "l"(p));
    return a;
}
__device__ __forceinline__ unsigned ctarank() {
    unsigned r; asm("mov.u32 %0, %%cluster_ctarank;" : "=r"(r)); return r;
}
__device__ __forceinline__ unsigned mapa_u32(unsigned local_addr, unsigned rank) {
    unsigned r;
    asm("mapa.shared::cluster.u32 %0, %1, %2;" : "=r"(r) : "r"(local_addr), "r"(rank));
    return r;
}
// Wait own-smem mbarrier for parity, acquire at CLUSTER scope (peers release).
__device__ __forceinline__ void mbar_wait_cluster(unsigned addr, unsigned parity) {
    unsigned done;
    asm volatile(
        "{\n\t.reg .pred p;\n\t"
        "mbarrier.try_wait.parity.acquire.cluster.shared::cta.b64 p, [%1], %2;\n\t"
        "selp.b32 %0, 1, 0, p;\n\t}"
        : "=r"(done) : "r"(addr), "r"(parity) : "memory");
    if (!done) {
        asm volatile(
            "{\n\t.reg .pred P1;\n\t"
            "W_%=:\n\t"
            "mbarrier.try_wait.parity.acquire.cluster.shared::cta.b64 P1, [%0], %1, 0x989680;\n\t"
            "@P1 bra.uni D_%=;\n\t"
            "bra.uni W_%=;\n\t"
            "D_%=:\n\t}"
            :: "r"(addr), "r"(parity) : "memory");
    }
}

// ---------------------------------------------------------------------------
// FPS kernel: cluster of 4 CTAs per batch, 256 threads/CTA, 8 pts/thread in
// packed f32x2 registers. Per iteration:
//   packed distance update -> warp REDUX argmax -> smem -> __syncthreads ->
//   all-warp REDUX => CTA result -> t0 remote-stores u64 key to all 4 CTAs'
//   DSMEM slots + release-arrives their mbarriers -> all threads acquire-wait
//   (parity) -> 4-way u64-key max -> winner coords from warmed L1.
// Distance numerics BITWISE identical to reference lowering:
//   d = fma(dz,dz, fma(dx,dx, fl(dy*dy))),  dx = c + (-l)
// Tie-break = lowest global index everywhere:
//   in-thread: ascending idx + strict '>'
//   warp/CTA: REDUX max on dist bits, REDUX min on idx among holders
//   cross-CTA: u64 key (dist_bits<<32)|~idx, strict '>' max scan in rank order
// ---------------------------------------------------------------------------
__global__ void __launch_bounds__(NTHR, 1) __cluster_dims__(CSIZE, 1, 1)
fps_kernel(const float* __restrict__ coords)
{
    __shared__ unsigned s_v[2][NWARP];
    __shared__ unsigned s_i[2][NWARP];
    __shared__ ull x_slot[2][CSIZE];      // cross-CTA exchange slots
    __shared__ ull x_mbar[2];             // parity-alternating mbarriers

    const int      b    = blockIdx.x >> 2;
    const unsigned rank = ctarank();
    const int      t    = threadIdx.x;
    const int      lane = t & 31;
    const int      wid  = t >> 5;
    const float* __restrict__ cb = coords + (size_t)b * LPTS * 3;
    const int base = rank * CPTS;         // this CTA's global point base

    const unsigned mb0   = smem_u32(&x_mbar[0]);
    const unsigned mb1   = smem_u32(&x_mbar[1]);
    const unsigned slot0 = smem_u32(&x_slot[0][0]);

    if (t == 0) {
        asm volatile("mbarrier.init.shared.b64 [%0], %1;" :: "r"(mb0), "r"(CSIZE) : "memory");
        asm volatile("mbarrier.init.shared.b64 [%0], %1;" :: "r"(mb1), "r"(CSIZE) : "memory");
    }
    __syncthreads();
    // All peers' mbarriers must be initialized before any remote arrive.
    asm volatile("barrier.cluster.arrive.aligned;" ::: "memory");
    asm volatile("barrier.cluster.wait.aligned;"   ::: "memory");
    // NOTE: cluster.sync flushes L1D -> warm the L1 AFTER this point.

    // Load this CTA's chunk into packed registers (pair = p, p+NTHR).
    ull cx[NPAIR], cy[NPAIR], cz[NPAIR];
    float md[PPT];
#pragma unroll
    for (int q = 0; q < NPAIR; q++) {
        const int p0 = base + t + (2 * q) * NTHR;
        const int p1 = p0 + NTHR;
        cx[q] = pk2(cb[p0 * 3 + 0], cb[p1 * 3 + 0]);
        cy[q] = pk2(cb[p0 * 3 + 1], cb[p1 * 3 + 1]);
        cz[q] = pk2(cb[p0 * 3 + 2], cb[p1 * 3 + 2]);
        md[2 * q]     = __int_as_float(0x7f800000);
        md[2 * q + 1] = __int_as_float(0x7f800000);
    }
    // Warm L1 with the WHOLE batch's coords (96KB < 228KB L1) so the
    // per-iteration winner refetch is an L1 hit regardless of owning rank.
    {
        const float4* c4 = (const float4*)cb;   // 8192*3/4 = 6144 vec4 loads
        for (int i = t; i < (LPTS * 3) / 4; i += NTHR) {
            float w0, w1, w2, w3;
            asm volatile("ld.global.nc.v4.f32 {%0,%1,%2,%3}, [%4];"
                         : "=f"(w0), "=f"(w1), "=f"(w2), "=f"(w3)
                         : "l"(c4 + i));
        }
    }

    if (rank == 0 && t == 0) g_fps_idx[b * MSEL] = 0;   // deterministic start
    float lx = cb[0], ly = cb[1], lz = cb[2];

    unsigned ph[2] = {0u, 0u};                // per-mbarrier phase parity

    for (int it = 1; it < MSEL; it++) {
        const int p = it & 1;
        const ull nlx = pk2(-lx, -lx);
        const ull nly = pk2(-ly, -ly);
        const ull nlz = pk2(-lz, -lz);

        float    bv = -1.0f;                  // distances are >= 0
        unsigned bi = 0xffffffffu;

#pragma unroll
        for (int q = 0; q < NPAIR; q++) {
            const ull dx = add2(cx[q], nlx);  // c + (-l) == c - l exactly
            const ull dy = add2(cy[q], nly);
            const ull dz = add2(cz[q], nlz);
            ull dd = mul2(dy, dy);            // fl(dy*dy) rounded alone
            dd = fma2(dx, dx, dd);
            dd = fma2(dz, dz, dd);
            float d0, d1; upk2(dd, d0, d1);
            const float m0 = fminf(md[2 * q],     d0);
            const float m1 = fminf(md[2 * q + 1], d1);
            md[2 * q]     = m0;
            md[2 * q + 1] = m1;
            // ascending global idx + strict '>' => lowest index on ties
            if (m0 > bv) { bv = m0; bi = base + t + (2 * q) * NTHR; }
            if (m1 > bv) { bv = m1; bi = base + t + (2 * q) * NTHR + NTHR; }
        }

        // Warp argmax (bits of non-negative floats are order-isomorphic).
        const unsigned vb   = __float_as_uint(bv);
        const unsigned wmax = __reduce_max_sync(0xffffffffu, vb);
        const unsigned wcnd = (vb == wmax) ? bi : 0xffffffffu;
        const unsigned wmin = __reduce_min_sync(0xffffffffu, wcnd);

        if (lane == 0) { s_v[p][wid] = wmax; s_i[p][wid] = wmin; }
        __syncthreads();

        // CTA-level result (all warps redundantly; 8 slots read 4x each —
        // duplicates are harmless for max / min-among-holders).
        const unsigned v    = s_v[p][lane & (NWARP - 1)];
        const unsigned i    = s_i[p][lane & (NWARP - 1)];
        const unsigned bmax = __reduce_max_sync(0xffffffffu, v);
        const unsigned cnd  = (v == bmax) ? i : 0xffffffffu;
        const unsigned bidx = __reduce_min_sync(0xffffffffu, cnd);

        // Cross-CTA exchange: t0 pushes this CTA's key into all 4 CTAs'
        // slot[p][rank] and release-arrives their mbar[p].
        if (t == 0) {
            const ull key = ((ull)bmax << 32) | (ull)(unsigned)(~bidx);
            const unsigned myslot = slot0 + (unsigned)(p * CSIZE + rank) * 8u;
#pragma unroll
            for (unsigned r = 0; r < CSIZE; r++) {
                const unsigned rs = mapa_u32(myslot, r);
                asm volatile("st.shared::cluster.u64 [%0], %1;"
                             :: "r"(rs), "l"(key) : "memory");
            }
            const unsigned mymb = p ? mb1 : mb0;
#pragma unroll
            for (unsigned r = 0; r < CSIZE; r++) {
                const unsigned rb = mapa_u32(mymb, r);
                asm volatile(
                    "mbarrier.arrive.release.cluster.shared::cluster.b64 _, [%0];"
                    :: "r"(rb) : "memory");
            }
        }

        // Wait for all 4 CTAs' arrivals (parity per mbarrier use count).
        mbar_wait_cluster(p ? mb1 : mb0, ph[p]);
        ph[p] ^= 1u;

        // 4-way combine in rank order; strict '>' on (dist<<32)|~idx keys
        // => max dist, lowest global index on ties.
        ull best = x_slot[p][0];
        best = (x_slot[p][1] > best) ? x_slot[p][1] : best;
        best = (x_slot[p][2] > best) ? x_slot[p][2] : best;
        best = (x_slot[p][3] > best) ? x_slot[p][3] : best;
        const unsigned gidx = ~(unsigned)best;

        if (rank == 0 && t == 0) g_fps_idx[b * MSEL + it] = (int)gidx;

        const float* pp = cb + (size_t)gidx * 3;     // warmed L1 hit
        lx = pp[0]; ly = pp[1]; lz = pp[2];
    }

    // No CTA may exit while peers could still remote-write its smem.
    asm volatile("barrier.cluster.arrive.aligned;" ::: "memory");
    asm volatile("barrier.cluster.wait.aligned;"   ::: "memory");
}

// ---------------------------------------------------------------------------
// Gather kernel: full-grid float4 copy of selected features + coords.
// d_out layout: coords_out [32*2048*3] floats, then feats_out [32*2048*128].
// ---------------------------------------------------------------------------
__global__ void gather_kernel(const float* __restrict__ coords,
                              const float* __restrict__ feats,
                              float* __restrict__ out)
{
    const int gid = blockIdx.x * blockDim.x + threadIdx.x;  // 32*2048*32
    const int row = gid >> 5;          // 0 .. 65535
    const int q   = gid & 31;          // float4 index within 128-float row
    const int b   = row >> 11;
    const int src = g_fps_idx[row];

    const float4* __restrict__ f =
        (const float4*)(feats + ((size_t)b * LPTS + src) * 128);
    float4* __restrict__ o =
        (float4*)(out + (size_t)BATCH * MSEL * 3 + (size_t)row * 128);
    o[q] = f[q];

    if (q == 0) {
        const float* c = coords + ((size_t)b * LPTS + src) * 3;
        float* oc = out + (size_t)row * 3;
        oc[0] = c[0];
        oc[1] = c[1];
        oc[2] = c[2];
    }
}

extern "C" void kernel_launch(void* const* d_in, const int* in_sizes, int n_in,
                              void* d_out, int out_size)
{
    const float* coords = (const float*)d_in[0];   // [32, 8192, 3]
    const float* feats  = (const float*)d_in[1];   // [32, 8192, 128]
    float* out = (float*)d_out;

    fps_kernel<<<BATCH * CSIZE, NTHR>>>(coords);   // 128 CTAs, clusters of 4

    const int total = BATCH * MSEL * 32;           // one thread per float4
    gather_kernel<<<total / 256, 256>>>(coords, feats, out);
}

// round 9
// speedup vs baseline: 3.5655x; 3.5655x over previous
#include <cuda_runtime.h>
#include <cstdint>

#define BATCH   32
#define LPTS    8192
#define MSEL    2048
#define CSIZE   4                    // CTAs per batch (cluster)
#define NTHR    256
#define NWARP   (NTHR / 32)          // 8 warps per CTA
#define NAGENT  (CSIZE * NWARP)      // 32 warp-agents per batch
#define APTS    (LPTS / NAGENT)      // 256 points per agent
#define PPT     (APTS / 32)          // 8 points per lane
#define NPAIR   (PPT / 2)            // 4 packed pairs

typedef unsigned long long ull;

// Selected indices, written by fps kernel, read by gather kernel.
__device__ int g_fps_idx[BATCH * MSEL];

// ---- Blackwell packed f32x2 helpers (per-lane rn rounding == scalar) ------
__device__ __forceinline__ ull pk2(float lo, float hi) {
    ull r; asm("mov.b64 %0, {%1,%2};" : "=l"(r) : "f"(lo), "f"(hi)); return r;
}
__device__ __forceinline__ void upk2(ull v, float& lo, float& hi) {
    asm("mov.b64 {%0,%1}, %2;" : "=f"(lo), "=f"(hi) : "l"(v));
}
__device__ __forceinline__ ull add2(ull a, ull b) {
    ull r; asm("add.rn.f32x2 %0, %1, %2;" : "=l"(r) : "l"(a), "l"(b)); return r;
}
__device__ __forceinline__ ull mul2(ull a, ull b) {
    ull r; asm("mul.rn.f32x2 %0, %1, %2;" : "=l"(r) : "l"(a), "l"(b)); return r;
}
__device__ __forceinline__ ull fma2(ull a, ull b, ull c) {
    ull r; asm("fma.rn.f32x2 %0, %1, %2, %3;" : "=l"(r) : "l"(a), "l"(b), "l"(c)); return r;
}
__device__ __forceinline__ unsigned smem_u32(const void* p) {
    unsigned a;
    asm("{ .reg .u64 t; cvta.to.shared.u64 t, %1; cvt.u32.u64 %0, t; }"
        : "=r"(a) : "l"(p));
    return a;
}
__device__ __forceinline__ unsigned ctarank() {
    unsigned r; asm("mov.u32 %0, %%cluster_ctarank;" : "=r"(r)); return r;
}
__device__ __forceinline__ unsigned mapa_u32(unsigned local_addr, unsigned rank) {
    unsigned r;
    asm("mapa.shared::cluster.u32 %0, %1, %2;" : "=r"(r) : "r"(local_addr), "r"(rank));
    return r;
}

// ---------------------------------------------------------------------------
// FPS kernel: 4-CTA cluster per batch; 32 warp-agents each own 256 points in
// packed f32x2 registers. NO mbarrier, NO __syncthreads in the loop:
//   compute -> warp REDUX key -> lanes 0..3 DSMEM-store the 64-bit key into
//   all 4 CTAs' slot[parity][agent] -> every warp volatile-polls its OWN
//   smem's 32 slots until all tags==it&7 -> REDUX global argmax -> refetch.
// Key = (dist_bits<<32) | ((8191-idx)<<3) | (it&7): tag and data share one
// word, so per-location coherence is the only ordering required; slots use
// parity-2 reuse and the it -> it+1 data dependency makes overwrite racing
// impossible.
// Distance numerics BITWISE identical to reference lowering (validated R6):
//   d = fma(dz,dz, fma(dx,dx, fl(dy*dy))),  dx = c + (-l)
// Tie-break = lowest global index at every level (exact jnp.argmax).
// ---------------------------------------------------------------------------
__global__ void __launch_bounds__(NTHR, 1) __cluster_dims__(CSIZE, 1, 1)
fps_kernel(const float* __restrict__ coords)
{
    __shared__ ull slots[2][NAGENT];      // 2 parities x 32 agents = 512B

    const int      b     = blockIdx.x >> 2;
    const unsigned rank  = ctarank();
    const int      t     = threadIdx.x;
    const int      lane  = t & 31;
    const int      wid   = t >> 5;
    const int      agent = (int)rank * NWARP + wid;    // 0..31
    const int      base  = agent * APTS;               // global point base
    const float* __restrict__ cb = coords + (size_t)b * LPTS * 3;

    // Zero slots (tag 0 != first tag 1), then make them cluster-visible.
    for (int i = t; i < 2 * NAGENT; i += NTHR) ((ull*)slots)[i] = 0ull;
    __syncthreads();
    asm volatile("barrier.cluster.arrive.aligned;" ::: "memory");
    asm volatile("barrier.cluster.wait.aligned;"   ::: "memory");
    // (cluster barrier flushes L1D -> warm L1 AFTER this point)

    // Precompute DSMEM addresses (mapa hoisted out of the loop).
    const unsigned s0 = smem_u32(&slots[0][agent]);
    const unsigned s1 = smem_u32(&slots[1][agent]);
    unsigned dst0 = 0, dst1 = 0;
    if (lane < CSIZE) {
        dst0 = mapa_u32(s0, (unsigned)lane);
        dst1 = mapa_u32(s1, (unsigned)lane);
    }
    const unsigned poll0 = smem_u32(&slots[0][lane]);
    const unsigned poll1 = smem_u32(&slots[1][lane]);

    // Load this agent's 256 points: lane p-index = base + lane + k*32.
    ull cx[NPAIR], cy[NPAIR], cz[NPAIR];
    float md[PPT];
#pragma unroll
    for (int q = 0; q < NPAIR; q++) {
        const int p0 = base + lane + (2 * q) * 32;
        const int p1 = p0 + 32;
        cx[q] = pk2(cb[p0 * 3 + 0], cb[p1 * 3 + 0]);
        cy[q] = pk2(cb[p0 * 3 + 1], cb[p1 * 3 + 1]);
        cz[q] = pk2(cb[p0 * 3 + 2], cb[p1 * 3 + 2]);
        md[2 * q]     = __int_as_float(0x7f800000);
        md[2 * q + 1] = __int_as_float(0x7f800000);
    }
    // Warm L1 with the whole batch's coords (96KB < 228KB L1) so the
    // per-iteration winner refetch is always an L1 hit.
    {
        const float4* c4 = (const float4*)cb;
        for (int i = t; i < (LPTS * 3) / 4; i += NTHR) {
            float w0, w1, w2, w3;
            asm volatile("ld.global.nc.v4.f32 {%0,%1,%2,%3}, [%4];"
                         : "=f"(w0), "=f"(w1), "=f"(w2), "=f"(w3)
                         : "l"(c4 + i));
        }
    }

    if (rank == 0 && t == 0) g_fps_idx[b * MSEL] = 0;   // deterministic start
    float lx = cb[0], ly = cb[1], lz = cb[2];

    for (int it = 1; it < MSEL; it++) {
        const int      p   = it & 1;
        const unsigned tag = (unsigned)it & 7u;
        const ull nlx = pk2(-lx, -lx);
        const ull nly = pk2(-ly, -ly);
        const ull nlz = pk2(-lz, -lz);

        float    bv = -1.0f;                  // distances are >= 0
        unsigned bi = 0xffffffffu;

#pragma unroll
        for (int q = 0; q < NPAIR; q++) {
            const ull dx = add2(cx[q], nlx);  // c + (-l) == c - l exactly
            const ull dy = add2(cy[q], nly);
            const ull dz = add2(cz[q], nlz);
            ull dd = mul2(dy, dy);            // fl(dy*dy) rounded alone
            dd = fma2(dx, dx, dd);
            dd = fma2(dz, dz, dd);
            float d0, d1; upk2(dd, d0, d1);
            const float m0 = fminf(md[2 * q],     d0);
            const float m1 = fminf(md[2 * q + 1], d1);
            md[2 * q]     = m0;
            md[2 * q + 1] = m1;
            // ascending global idx + strict '>' => lowest index on ties
            if (m0 > bv) { bv = m0; bi = (unsigned)(base + lane + (2 * q) * 32); }
            if (m1 > bv) { bv = m1; bi = (unsigned)(base + lane + (2 * q) * 32 + 32); }
        }

        // Warp argmax (bits of non-negative floats are order-isomorphic).
        const unsigned vb   = __float_as_uint(bv);
        const unsigned wmax = __reduce_max_sync(0xffffffffu, vb);
        const unsigned wcnd = (vb == wmax) ? bi : 0xffffffffu;
        const unsigned wmin = __reduce_min_sync(0xffffffffu, wcnd);

        // Ship this agent's key to all 4 CTAs (lanes 0..3, one rank each).
        const ull key = ((ull)wmax << 32)
                      | ((ull)((8191u - wmin) & 0x1fffu) << 3)
                      | (ull)tag;
        if (lane < CSIZE) {
            const unsigned dst = p ? dst1 : dst0;
            asm volatile("st.relaxed.cluster.shared::cluster.u64 [%0], %1;"
                         :: "r"(dst), "l"(key) : "memory");
        }

        // Poll OWN smem: lane l watches slot[p][l]; spin until all 32 fresh.
        const unsigned pa = p ? poll1 : poll0;
        ull k;
        bool ok;
        do {
            asm volatile("ld.volatile.shared.u64 %0, [%1];" : "=l"(k) : "r"(pa));
            ok = (((unsigned)k & 7u) == tag);
        } while (!__all_sync(0xffffffffu, ok));

        // Global argmax over the 32 agent keys:
        // max dist bits, then max (8191-idx) field = lowest index (tags equal).
        const unsigned hi   = (unsigned)(k >> 32);
        const unsigned hmax = __reduce_max_sync(0xffffffffu, hi);
        const unsigned cl   = (hi == hmax) ? (unsigned)k : 0u;
        const unsigned cmax = __reduce_max_sync(0xffffffffu, cl);
        const unsigned gidx = 8191u - ((cmax >> 3) & 0x1fffu);

        if (rank == 0 && wid == 0 && lane == 0)
            g_fps_idx[b * MSEL + it] = (int)gidx;

        const float* pp = cb + (size_t)gidx * 3;     // warmed L1 hit
        lx = pp[0]; ly = pp[1]; lz = pp[2];
    }

    // No CTA may exit while peers could still remote-write its smem.
    asm volatile("barrier.cluster.arrive.aligned;" ::: "memory");
    asm volatile("barrier.cluster.wait.aligned;"   ::: "memory");
}

// ---------------------------------------------------------------------------
// Gather kernel: thread = quarter feature row (8 float4s, MLP 8; single wave).
// d_out layout: coords_out [32*2048*3] floats, then feats_out [32*2048*128].
// ---------------------------------------------------------------------------
__global__ void gather_kernel(const float* __restrict__ coords,
                              const float* __restrict__ feats,
                              float* __restrict__ out)
{
    const int gid  = blockIdx.x * blockDim.x + threadIdx.x;  // 65536*4 threads
    const int row  = gid >> 2;            // 0 .. 65535
    const int part = gid & 3;             // quarter of the 128-float row
    const int b    = row >> 11;
    const int src  = g_fps_idx[row];

    const float4* __restrict__ f =
        (const float4*)(feats + ((size_t)b * LPTS + src) * 128) + part * 8;
    float4* __restrict__ o =
        (float4*)(out + (size_t)BATCH * MSEL * 3) + (size_t)row * 32 + part * 8;

    float4 r[8];
#pragma unroll
    for (int i = 0; i < 8; i++) r[i] = f[i];   // 8 independent loads (MLP 8)
#pragma unroll
    for (int i = 0; i < 8; i++) o[i] = r[i];

    if (part == 0) {
        const float* c = coords + ((size_t)b * LPTS + src) * 3;
        float* oc = out + (size_t)row * 3;
        oc[0] = c[0];
        oc[1] = c[1];
        oc[2] = c[2];
    }
}

extern "C" void kernel_launch(void* const* d_in, const int* in_sizes, int n_in,
                              void* d_out, int out_size)
{
    const float* coords = (const float*)d_in[0];   // [32, 8192, 3]
    const float* feats  = (const float*)d_in[1];   // [32, 8192, 128]
    float* out = (float*)d_out;

    fps_kernel<<<BATCH * CSIZE, NTHR>>>(coords);   // 128 CTAs, clusters of 4

    const int total = BATCH * MSEL * 4;            // thread per quarter-row
    gather_kernel<<<total / 256, 256>>>(coords, feats, out);
}